// round 1
// baseline (speedup 1.0000x reference)
#include <cuda_runtime.h>
#include <cstdint>

#define Bsz 32
#define Ssz 4096
#define Dsz 1280
#define Rsz 64
// combined rank = 128

// Scratch for H = x @ Acat^T : 31 * 4096 * 128 floats (~65 MB)
__device__ float g_H[31u * Ssz * 128];

__device__ __forceinline__ unsigned f2tf32(float f) {
    unsigned u;
    asm("cvt.rna.tf32.f32 %0, %1;" : "=r"(u) : "f"(f));
    return u;
}

__device__ __forceinline__ void mma_tf32(float c[4], const unsigned a[4], const unsigned b[2]) {
    asm volatile(
        "mma.sync.aligned.m16n8k8.row.col.f32.tf32.tf32.f32 "
        "{%0,%1,%2,%3}, {%4,%5,%6,%7}, {%8,%9}, {%0,%1,%2,%3};"
        : "+f"(c[0]), "+f"(c[1]), "+f"(c[2]), "+f"(c[3])
        : "r"(a[0]), "r"(a[1]), "r"(a[2]), "r"(a[3]), "r"(b[0]), "r"(b[1]));
}

// ---------------------------------------------------------------------------
// GEMM1: H[b] (4096 x 128) = x[b] (4096 x 1280) @ Acat[b]^T (1280 x 128)
// Acat rows: n<64 -> A_experts[label[b]][n][:], n>=64 -> A_gen[n-64][:]
// grid (32, 31), block 256. CTA tile 128x128, K-tile 32 (40 iters).
// ---------------------------------------------------------------------------
__global__ __launch_bounds__(256) void gemm1_kernel(
    const float* __restrict__ x,
    const float* __restrict__ A_exp,
    const float* __restrict__ A_gen,
    const int*   __restrict__ label)
{
    const int b  = blockIdx.y;
    const int m0 = blockIdx.x * 128;
    const int e  = label[b];

    __shared__ unsigned xs[128][36];
    __shared__ unsigned as[128][36];

    const int tid  = threadIdx.x;
    const int lane = tid & 31;
    const int warp = tid >> 5;
    const int wm   = warp & 3;   // 4 warps along M (32 rows each)
    const int wn   = warp >> 2;  // 2 warps along N (64 cols each)
    const int lg   = lane >> 2;  // group id 0..7
    const int lc   = lane & 3;   // thread-in-group 0..3

    const float* xbase = x + ((size_t)b * Ssz + m0) * Dsz;

    float acc[2][8][4] = {};

    float4 px[4], pa[4];

    auto g_load = [&](int kt) {
#pragma unroll
        for (int i = 0; i < 4; i++) {
            int v = tid + i * 256;
            int row = v >> 3, c4 = v & 7;
            px[i] = *(const float4*)(xbase + (size_t)row * Dsz + kt * 32 + c4 * 4);
            const float* ap = (row < Rsz)
                ? (A_exp + ((size_t)e * Rsz + row) * Dsz)
                : (A_gen + (size_t)(row - Rsz) * Dsz);
            pa[i] = *(const float4*)(ap + kt * 32 + c4 * 4);
        }
    };
    auto s_store = [&]() {
#pragma unroll
        for (int i = 0; i < 4; i++) {
            int v = tid + i * 256;
            int row = v >> 3, c4 = v & 7;
            uint4 tx, ta;
            tx.x = f2tf32(px[i].x); tx.y = f2tf32(px[i].y);
            tx.z = f2tf32(px[i].z); tx.w = f2tf32(px[i].w);
            ta.x = f2tf32(pa[i].x); ta.y = f2tf32(pa[i].y);
            ta.z = f2tf32(pa[i].z); ta.w = f2tf32(pa[i].w);
            *(uint4*)&xs[row][c4 * 4] = tx;
            *(uint4*)&as[row][c4 * 4] = ta;
        }
    };

    g_load(0);
    s_store();
    __syncthreads();

    const int KT = Dsz / 32;  // 40
    for (int kt = 0; kt < KT; kt++) {
        if (kt + 1 < KT) g_load(kt + 1);

#pragma unroll
        for (int kk = 0; kk < 32; kk += 8) {
            unsigned af[2][4];
            unsigned bf[8][2];
#pragma unroll
            for (int i = 0; i < 2; i++) {
                int r = wm * 32 + i * 16 + lg;
                af[i][0] = xs[r][kk + lc];
                af[i][1] = xs[r + 8][kk + lc];
                af[i][2] = xs[r][kk + lc + 4];
                af[i][3] = xs[r + 8][kk + lc + 4];
            }
#pragma unroll
            for (int j = 0; j < 8; j++) {
                int n = wn * 64 + j * 8 + lg;
                bf[j][0] = as[n][kk + lc];
                bf[j][1] = as[n][kk + lc + 4];
            }
#pragma unroll
            for (int i = 0; i < 2; i++)
#pragma unroll
                for (int j = 0; j < 8; j++)
                    mma_tf32(acc[i][j], af[i], bf[j]);
        }
        __syncthreads();
        if (kt + 1 < KT) {
            s_store();
            __syncthreads();
        }
    }

    // epilogue -> g_H
    float* Hb = g_H + ((size_t)b * Ssz + m0) * 128;
#pragma unroll
    for (int i = 0; i < 2; i++) {
        int r = wm * 32 + i * 16 + lg;
#pragma unroll
        for (int j = 0; j < 8; j++) {
            int c = wn * 64 + j * 8 + lc * 2;
            *(float2*)&Hb[(size_t)r * 128 + c]       = make_float2(acc[i][j][0], acc[i][j][1]);
            *(float2*)&Hb[(size_t)(r + 8) * 128 + c] = make_float2(acc[i][j][2], acc[i][j][3]);
        }
    }
}

// ---------------------------------------------------------------------------
// GEMM2: out[b] (4096 x 1280) = 2 * H[b] (4096 x 128) @ Bcat[b]^T (128 x 1280)
// Bcat[d][k]: k<64 -> B_experts[e][d][k], k>=64 -> B_gen[d][k-64]
// grid (32, 10, 31), block 256. CTA tile 128x128, K-tile 32 (4 iters).
// ---------------------------------------------------------------------------
__global__ __launch_bounds__(256) void gemm2_kernel(
    const float* __restrict__ B_exp,
    const float* __restrict__ B_gen,
    const int*   __restrict__ label,
    float*       __restrict__ out)
{
    const int b  = blockIdx.z;
    const int m0 = blockIdx.x * 128;
    const int n0 = blockIdx.y * 128;
    const int e  = label[b];

    __shared__ unsigned hs[128][36];
    __shared__ unsigned bs[128][36];

    const int tid  = threadIdx.x;
    const int lane = tid & 31;
    const int warp = tid >> 5;
    const int wm   = warp & 3;
    const int wn   = warp >> 2;
    const int lg   = lane >> 2;
    const int lc   = lane & 3;

    const float* Hb = g_H + ((size_t)b * Ssz + m0) * 128;

    float acc[2][8][4] = {};
    float4 ph[4], pb[4];

    auto g_load = [&](int kt) {
#pragma unroll
        for (int i = 0; i < 4; i++) {
            int v = tid + i * 256;
            int row = v >> 3, c4 = v & 7;
            ph[i] = *(const float4*)(Hb + (size_t)row * 128 + kt * 32 + c4 * 4);
            int d = n0 + row;
            const float* bp = (kt < 2)
                ? (B_exp + ((size_t)e * Dsz + d) * Rsz + kt * 32)
                : (B_gen + (size_t)d * Rsz + (kt - 2) * 32);
            pb[i] = *(const float4*)(bp + c4 * 4);
        }
    };
    auto s_store = [&]() {
#pragma unroll
        for (int i = 0; i < 4; i++) {
            int v = tid + i * 256;
            int row = v >> 3, c4 = v & 7;
            uint4 th, tb;
            th.x = f2tf32(ph[i].x); th.y = f2tf32(ph[i].y);
            th.z = f2tf32(ph[i].z); th.w = f2tf32(ph[i].w);
            tb.x = f2tf32(pb[i].x); tb.y = f2tf32(pb[i].y);
            tb.z = f2tf32(pb[i].z); tb.w = f2tf32(pb[i].w);
            *(uint4*)&hs[row][c4 * 4] = th;
            *(uint4*)&bs[row][c4 * 4] = tb;
        }
    };

    g_load(0);
    s_store();
    __syncthreads();

    const int KT = 4;
    for (int kt = 0; kt < KT; kt++) {
        if (kt + 1 < KT) g_load(kt + 1);

#pragma unroll
        for (int kk = 0; kk < 32; kk += 8) {
            unsigned af[2][4];
            unsigned bf[8][2];
#pragma unroll
            for (int i = 0; i < 2; i++) {
                int r = wm * 32 + i * 16 + lg;
                af[i][0] = hs[r][kk + lc];
                af[i][1] = hs[r + 8][kk + lc];
                af[i][2] = hs[r][kk + lc + 4];
                af[i][3] = hs[r + 8][kk + lc + 4];
            }
#pragma unroll
            for (int j = 0; j < 8; j++) {
                int n = wn * 64 + j * 8 + lg;
                bf[j][0] = bs[n][kk + lc];
                bf[j][1] = bs[n][kk + lc + 4];
            }
#pragma unroll
            for (int i = 0; i < 2; i++)
#pragma unroll
                for (int j = 0; j < 8; j++)
                    mma_tf32(acc[i][j], af[i], bf[j]);
        }
        __syncthreads();
        if (kt + 1 < KT) {
            s_store();
            __syncthreads();
        }
    }

    // epilogue: out = 2 * acc
    float* ob = out + ((size_t)b * Ssz + m0) * Dsz + n0;
#pragma unroll
    for (int i = 0; i < 2; i++) {
        int r = wm * 32 + i * 16 + lg;
#pragma unroll
        for (int j = 0; j < 8; j++) {
            int c = wn * 64 + j * 8 + lc * 2;
            *(float2*)&ob[(size_t)r * Dsz + c] =
                make_float2(2.0f * acc[i][j][0], 2.0f * acc[i][j][1]);
            *(float2*)&ob[(size_t)(r + 8) * Dsz + c] =
                make_float2(2.0f * acc[i][j][2], 2.0f * acc[i][j][3]);
        }
    }
}

// Zero out sample b = 31 (reference loops range(B-1))
__global__ void zero_last_kernel(float* __restrict__ out)
{
    size_t i = (size_t)blockIdx.x * blockDim.x + threadIdx.x;
    float4* p = (float4*)(out + (size_t)(Bsz - 1) * Ssz * Dsz);
    if (i < (size_t)Ssz * Dsz / 4)
        p[i] = make_float4(0.f, 0.f, 0.f, 0.f);
}

extern "C" void kernel_launch(void* const* d_in, const int* in_sizes, int n_in,
                              void* d_out, int out_size)
{
    const float* x     = (const float*)d_in[0];
    // d_in[1] = weight : unused by the reference
    const float* A_exp = (const float*)d_in[2];
    const float* B_exp = (const float*)d_in[3];
    const float* A_gen = (const float*)d_in[4];
    const float* B_gen = (const float*)d_in[5];
    const int*   label = (const int*)d_in[6];
    float* out = (float*)d_out;

    gemm1_kernel<<<dim3(Ssz / 128, Bsz - 1), 256>>>(x, A_exp, A_gen, label);
    gemm2_kernel<<<dim3(Ssz / 128, Dsz / 128, Bsz - 1), 256>>>(B_exp, B_gen, label, out);
    zero_last_kernel<<<(Ssz * Dsz / 4 + 255) / 256, 256>>>(out);
}

// round 3
// speedup vs baseline: 1.0276x; 1.0276x over previous
#include <cuda_runtime.h>
#include <cstdint>

#define Bsz 32
#define Ssz 4096
#define Dsz 1280
#define Rsz 64

// Scratch for H = x @ Acat^T : 31 * 4096 * 128 floats (~65 MB)
__device__ float g_H[31u * Ssz * 128];

// stage: 128 rows x 144 bytes (32 floats + 4 pad, 16B aligned, conflict-free)
#define STG 18432
#define NSTAGE 3
#define SMEM_BYTES (2 * NSTAGE * STG)   // 110592

// ---------------------------------------------------------------------------
// helpers
// ---------------------------------------------------------------------------
__device__ __forceinline__ uint32_t smem_u32(const void* p) {
    uint32_t a;
    asm("{ .reg .u64 t; cvta.to.shared.u64 t, %1; cvt.u32.u64 %0, t; }" : "=r"(a) : "l"(p));
    return a;
}

__device__ __forceinline__ unsigned f2tf32(float f) {
    unsigned u;
    asm("cvt.rna.tf32.f32 %0, %1;" : "=r"(u) : "f"(f));
    return u;
}

__device__ __forceinline__ unsigned lds_cvt(uint32_t addr) {
    float f;
    asm("ld.shared.f32 %0, [%1];" : "=f"(f) : "r"(addr));
    return f2tf32(f);
}

__device__ __forceinline__ void cp16(uint32_t dst, const void* src) {
    asm volatile("cp.async.cg.shared.global [%0], [%1], 16;" :: "r"(dst), "l"(src));
}

__device__ __forceinline__ void commit_group() {
    asm volatile("cp.async.commit_group;" ::: "memory");
}

__device__ __forceinline__ void mma_tf32(float c[4], const unsigned a[4], const unsigned b[2]) {
    asm volatile(
        "mma.sync.aligned.m16n8k8.row.col.f32.tf32.tf32.f32 "
        "{%0,%1,%2,%3}, {%4,%5,%6,%7}, {%8,%9}, {%0,%1,%2,%3};"
        : "+f"(c[0]), "+f"(c[1]), "+f"(c[2]), "+f"(c[3])
        : "r"(a[0]), "r"(a[1]), "r"(a[2]), "r"(a[3]), "r"(b[0]), "r"(b[1]));
}

// ---------------------------------------------------------------------------
// GEMM1: H[b] (4096x128) = x[b] (4096x1280) @ Acat[b]^T
// grid (32, 31), 128 thr (4 warps, 2Mx2N, warp tile 64x64). K stage 32, S=3.
// ---------------------------------------------------------------------------
__global__ __launch_bounds__(128) void gemm1_tc(
    const float* __restrict__ x,
    const float* __restrict__ A_exp,
    const float* __restrict__ A_gen,
    const int*   __restrict__ label)
{
    extern __shared__ char smem[];
    const int b   = blockIdx.y;
    const int m0  = blockIdx.x * 128;
    const int e   = __ldg(&label[b]);
    const int tid = threadIdx.x;
    const int warp = tid >> 5, lane = tid & 31;
    const int wm = warp & 1, wn = warp >> 1;
    const int lg = lane >> 2, lc = lane & 3;

    uint32_t sA = smem_u32(smem);
    uint32_t sB = sA + NSTAGE * STG;

    const char* xb = (const char*)(x + ((size_t)b * Ssz + m0) * Dsz);
    const char* Ae = (const char*)(A_exp + (size_t)e * Rsz * Dsz);
    const char* Ag = (const char*)A_gen;

    const int tr = tid >> 3;            // 0..15
    const int cb = (tid & 7) * 16;      // byte chunk in 128B row

    auto load_stage = [&](int j) {
        uint32_t dA = sA + (j % NSTAGE) * STG;
        uint32_t dB = sB + (j % NSTAGE) * STG;
#pragma unroll
        for (int i = 0; i < 8; i++) {
            int row = i * 16 + tr;
            cp16(dA + row * 144 + cb, xb + (size_t)row * (Dsz * 4) + j * 128 + cb);
            const char* src = (i < 4)
                ? (Ae + (size_t)row * (Dsz * 4) + j * 128 + cb)
                : (Ag + (size_t)(row - Rsz) * (Dsz * 4) + j * 128 + cb);
            cp16(dB + row * 144 + cb, src);
        }
        commit_group();
    };

    load_stage(0);
    load_stage(1);

    float acc[4][8][4] = {};

    const int KT = Dsz / 32;   // 40
#pragma unroll 1
    for (int kt = 0; kt < KT; kt++) {
        asm volatile("cp.async.wait_group 1;" ::: "memory");
        __syncthreads();
        if (kt + 2 < KT) load_stage(kt + 2);
        else             commit_group();   // keep wait_group accounting

        uint32_t aS = sA + (kt % NSTAGE) * STG;
        uint32_t bS = sB + (kt % NSTAGE) * STG;

#pragma unroll
        for (int kk = 0; kk < 32; kk += 8) {
            unsigned af[4][4], bf[8][2];
#pragma unroll
            for (int i = 0; i < 4; i++) {
                int r = wm * 64 + i * 16 + lg;
                uint32_t base = aS + r * 144 + (kk + lc) * 4;
                af[i][0] = lds_cvt(base);
                af[i][1] = lds_cvt(base + 8 * 144);
                af[i][2] = lds_cvt(base + 16);
                af[i][3] = lds_cvt(base + 8 * 144 + 16);
            }
#pragma unroll
            for (int j = 0; j < 8; j++) {
                int n = wn * 64 + j * 8 + lg;
                uint32_t base = bS + n * 144 + (kk + lc) * 4;
                bf[j][0] = lds_cvt(base);
                bf[j][1] = lds_cvt(base + 16);
            }
#pragma unroll
            for (int i = 0; i < 4; i++)
#pragma unroll
                for (int j = 0; j < 8; j++)
                    mma_tf32(acc[i][j], af[i], bf[j]);
        }
    }

    // epilogue -> g_H
    float* Hb = g_H + ((size_t)b * Ssz + m0) * 128;
#pragma unroll
    for (int i = 0; i < 4; i++) {
        int r = wm * 64 + i * 16 + lg;
#pragma unroll
        for (int j = 0; j < 8; j++) {
            int c = wn * 64 + j * 8 + lc * 2;
            *(float2*)&Hb[(size_t)r * 128 + c]       = make_float2(acc[i][j][0], acc[i][j][1]);
            *(float2*)&Hb[(size_t)(r + 8) * 128 + c] = make_float2(acc[i][j][2], acc[i][j][3]);
        }
    }
}

// ---------------------------------------------------------------------------
// GEMM2: out[b] (4096x1280) = 2 * H[b] (4096x128) @ Bcat[b]^T
// grid (32, 10, 32), 128 thr, warp tile 64x64. K stage 32, KT=4, S=3.
// b==31 CTAs zero their tile (reference zeroes the last sample).
// ---------------------------------------------------------------------------
__global__ __launch_bounds__(128) void gemm2_tc(
    const float* __restrict__ B_exp,
    const float* __restrict__ B_gen,
    const int*   __restrict__ label,
    float*       __restrict__ out)
{
    extern __shared__ char smem[];
    const int b   = blockIdx.z;
    const int m0  = blockIdx.x * 128;
    const int n0  = blockIdx.y * 128;
    const int tid = threadIdx.x;

    float* ob = out + ((size_t)b * Ssz + m0) * Dsz + n0;

    if (b == Bsz - 1) {
        float4 z = make_float4(0.f, 0.f, 0.f, 0.f);
#pragma unroll
        for (int i = 0; i < 32; i++) {
            int v = tid + i * 128;       // 4096 float4 = 128 rows x 32
            int row = v >> 5, c4 = v & 31;
            __stcs((float4*)(ob + (size_t)row * Dsz + c4 * 4), z);
        }
        return;
    }

    const int e = __ldg(&label[b]);
    const int warp = tid >> 5, lane = tid & 31;
    const int wm = warp & 1, wn = warp >> 1;
    const int lg = lane >> 2, lc = lane & 3;

    uint32_t sA = smem_u32(smem);
    uint32_t sB = sA + NSTAGE * STG;

    const char* Hb = (const char*)(g_H + ((size_t)b * Ssz + m0) * 128);

    const int tr = tid >> 3;
    const int cb = (tid & 7) * 16;

    auto load_stage = [&](int j) {
        uint32_t dA = sA + (j % NSTAGE) * STG;
        uint32_t dB = sB + (j % NSTAGE) * STG;
#pragma unroll
        for (int i = 0; i < 8; i++) {
            int row = i * 16 + tr;
            cp16(dA + row * 144 + cb, Hb + (size_t)row * 512 + j * 128 + cb);
            int d = n0 + row;
            const char* src = (j < 2)
                ? ((const char*)B_exp + ((size_t)e * Dsz + d) * 256 + j * 128 + cb)
                : ((const char*)B_gen + (size_t)d * 256 + (j - 2) * 128 + cb);
            cp16(dB + row * 144 + cb, src);
        }
        commit_group();
    };

    load_stage(0);
    load_stage(1);

    float acc[4][8][4] = {};

    const int KT = 4;
#pragma unroll 1
    for (int kt = 0; kt < KT; kt++) {
        asm volatile("cp.async.wait_group 1;" ::: "memory");
        __syncthreads();
        if (kt + 2 < KT) load_stage(kt + 2);
        else             commit_group();

        uint32_t aS = sA + (kt % NSTAGE) * STG;
        uint32_t bS = sB + (kt % NSTAGE) * STG;

#pragma unroll
        for (int kk = 0; kk < 32; kk += 8) {
            unsigned af[4][4], bf[8][2];
#pragma unroll
            for (int i = 0; i < 4; i++) {
                int r = wm * 64 + i * 16 + lg;
                uint32_t base = aS + r * 144 + (kk + lc) * 4;
                af[i][0] = lds_cvt(base);
                af[i][1] = lds_cvt(base + 8 * 144);
                af[i][2] = lds_cvt(base + 16);
                af[i][3] = lds_cvt(base + 8 * 144 + 16);
            }
#pragma unroll
            for (int j = 0; j < 8; j++) {
                int n = wn * 64 + j * 8 + lg;
                uint32_t base = bS + n * 144 + (kk + lc) * 4;
                bf[j][0] = lds_cvt(base);
                bf[j][1] = lds_cvt(base + 16);
            }
#pragma unroll
            for (int i = 0; i < 4; i++)
#pragma unroll
                for (int j = 0; j < 8; j++)
                    mma_tf32(acc[i][j], af[i], bf[j]);
        }
    }

    // epilogue: out = 2 * acc, streaming stores
#pragma unroll
    for (int i = 0; i < 4; i++) {
        int r = wm * 64 + i * 16 + lg;
#pragma unroll
        for (int j = 0; j < 8; j++) {
            int c = wn * 64 + j * 8 + lc * 2;
            __stcs((float2*)&ob[(size_t)r * Dsz + c],
                   make_float2(2.0f * acc[i][j][0], 2.0f * acc[i][j][1]));
            __stcs((float2*)&ob[(size_t)(r + 8) * Dsz + c],
                   make_float2(2.0f * acc[i][j][2], 2.0f * acc[i][j][3]));
        }
    }
}

// ---------------------------------------------------------------------------
extern "C" void kernel_launch(void* const* d_in, const int* in_sizes, int n_in,
                              void* d_out, int out_size)
{
    const float* x     = (const float*)d_in[0];
    // d_in[1] = weight : unused by the reference
    const float* A_exp = (const float*)d_in[2];
    const float* B_exp = (const float*)d_in[3];
    const float* A_gen = (const float*)d_in[4];
    const float* B_gen = (const float*)d_in[5];
    const int*   label = (const int*)d_in[6];
    float* out = (float*)d_out;

    cudaFuncSetAttribute(gemm1_tc, cudaFuncAttributeMaxDynamicSharedMemorySize, SMEM_BYTES);
    cudaFuncSetAttribute(gemm2_tc, cudaFuncAttributeMaxDynamicSharedMemorySize, SMEM_BYTES);

    gemm1_tc<<<dim3(Ssz / 128, Bsz - 1), 128, SMEM_BYTES>>>(x, A_exp, A_gen, label);
    gemm2_tc<<<dim3(Ssz / 128, Dsz / 128, Bsz), 128, SMEM_BYTES>>>(B_exp, B_gen, label, out);
}

// round 4
// speedup vs baseline: 1.3439x; 1.3079x over previous
#include <cuda_runtime.h>
#include <cuda_fp16.h>
#include <cstdint>
#include <cstring>

#define Bsz 32
#define Ssz 4096
#define Dsz 1280
#define Rsz 64

// fp16 scratch: concatenated pre-rounded params + intermediate H
__device__ __half g_Acat[8 * 128 * Dsz];          // [e][n(128)][k(1280)]
__device__ __half g_Bcat[8 * Dsz * 128];          // [e][d(1280)][k(128)]
__device__ __half g_H[31u * Ssz * 128];           // [b][m][k(128)]

#define STGA 18432          // 128 rows x 144B (64 halves + pad)
#define STGH 34816          // 128 rows x 272B (128 halves + pad)
#define SMEM1 (2 * STGA + 3 * STGA)    // 92160
#define SMEM2 (STGH + 2 * STGH)        // 104448

// ---------------------------------------------------------------------------
__device__ __forceinline__ uint32_t smem_u32(const void* p) {
    uint32_t a;
    asm("{ .reg .u64 t; cvta.to.shared.u64 t, %1; cvt.u32.u64 %0, t; }" : "=r"(a) : "l"(p));
    return a;
}
__device__ __forceinline__ unsigned h2u(__half2 h) {
    unsigned u; memcpy(&u, &h, 4); return u;
}
__device__ __forceinline__ void cp16(uint32_t dst, const void* src) {
    asm volatile("cp.async.cg.shared.global [%0], [%1], 16;" :: "r"(dst), "l"(src));
}
__device__ __forceinline__ void commit_group() {
    asm volatile("cp.async.commit_group;" ::: "memory");
}
__device__ __forceinline__ void sts128(uint32_t a, unsigned u0, unsigned u1, unsigned u2, unsigned u3) {
    asm volatile("st.shared.v4.b32 [%0], {%1,%2,%3,%4};" :: "r"(a), "r"(u0), "r"(u1), "r"(u2), "r"(u3));
}
__device__ __forceinline__ void ldsm_x4(unsigned r[4], uint32_t addr) {
    asm volatile("ldmatrix.sync.aligned.m8n8.x4.shared.b16 {%0,%1,%2,%3}, [%4];"
                 : "=r"(r[0]), "=r"(r[1]), "=r"(r[2]), "=r"(r[3]) : "r"(addr));
}
__device__ __forceinline__ void mma16816(float c[4], const unsigned a[4], unsigned b0, unsigned b1) {
    asm volatile(
        "mma.sync.aligned.m16n8k16.row.col.f32.f16.f16.f32 "
        "{%0,%1,%2,%3}, {%4,%5,%6,%7}, {%8,%9}, {%0,%1,%2,%3};"
        : "+f"(c[0]), "+f"(c[1]), "+f"(c[2]), "+f"(c[3])
        : "r"(a[0]), "r"(a[1]), "r"(a[2]), "r"(a[3]), "r"(b0), "r"(b1));
}

// ---------------------------------------------------------------------------
// Pre-convert params to fp16 concatenated layouts (rn rounding).
// ---------------------------------------------------------------------------
__global__ void preconv_kernel(const float* __restrict__ A_exp,
                               const float* __restrict__ B_exp,
                               const float* __restrict__ A_gen,
                               const float* __restrict__ B_gen)
{
    int idx = blockIdx.x * blockDim.x + threadIdx.x;     // half2-pair index
    const int NA = 8 * 128 * Dsz / 2;                    // 655360
    if (idx < NA) {
        int p = idx * 2;
        int e = p / (128 * Dsz);
        int r = p % (128 * Dsz);
        int n = r / Dsz, k = r % Dsz;
        float f0, f1;
        if (n < Rsz) {
            const float* s = A_exp + ((size_t)e * Rsz + n) * Dsz + k;
            f0 = s[0]; f1 = s[1];
        } else {
            const float* s = A_gen + (size_t)(n - Rsz) * Dsz + k;
            f0 = s[0]; f1 = s[1];
        }
        *reinterpret_cast<__half2*>(&g_Acat[p]) = __floats2half2_rn(f0, f1);

        // Bcat same element count
        int e2 = p / (Dsz * 128);
        int r2 = p % (Dsz * 128);
        int d = r2 / 128, k2 = r2 % 128;
        float g0, g1;
        if (k2 < Rsz) {
            const float* s = B_exp + ((size_t)e2 * Dsz + d) * Rsz + k2;
            g0 = s[0]; g1 = s[1];
        } else {
            const float* s = B_gen + (size_t)d * Rsz + (k2 - Rsz);
            g0 = s[0]; g1 = s[1];
        }
        *reinterpret_cast<__half2*>(&g_Bcat[p]) = __floats2half2_rn(g0, g1);
    }
}

// ---------------------------------------------------------------------------
// GEMM1: H[b] (4096x128) = x[b] @ Acat[b]^T, fp16 mma, output fp16 to g_H.
// grid (32, 31), 128 thr (4 warps 2Mx2N, warp tile 64x64). K-stage 64, KT=20.
// ---------------------------------------------------------------------------
__global__ __launch_bounds__(128) void gemm1_fp16(
    const float* __restrict__ x,
    const int*   __restrict__ label)
{
    extern __shared__ char smem[];
    const int b   = blockIdx.y;
    const int m0  = blockIdx.x * 128;
    const int e   = __ldg(&label[b]);
    const int tid = threadIdx.x;
    const int warp = tid >> 5, lane = tid & 31;
    const int wm = warp & 1, wn = warp >> 1;
    const int lg = lane >> 2, lc = lane & 3;

    uint32_t sX = smem_u32(smem);                 // x ring: 2 stages
    uint32_t sA = sX + 2 * STGA;                  // Acat ring: 3 stages

    const char* xb = (const char*)(x + ((size_t)b * Ssz + m0) * Dsz);
    const char* Ab = (const char*)g_Acat + (size_t)e * 128 * Dsz * 2;

    // ldmatrix per-lane offsets (stride 144)
    uint32_t aoff[4], boff[4];
#pragma unroll
    for (int i = 0; i < 4; i++)
        aoff[i] = (uint32_t)((wm * 64 + i * 16 + (lane & 15)) * 144 + ((lane >> 4) << 4));
#pragma unroll
    for (int jp = 0; jp < 4; jp++)
        boff[jp] = (uint32_t)((wn * 64 + jp * 16 + (lane & 7) + ((lane >> 4) << 3)) * 144
                              + (((lane >> 3) & 1) << 4));

    auto cp_A = [&](int j) {
        uint32_t dst = sA + (j % 3) * STGA;
        const char* base = Ab + (size_t)j * 128;   // k-slice j*64 halves = 128B
#pragma unroll
        for (int i = 0; i < 8; i++) {
            int cid = tid + i * 128;
            int row = cid >> 3, g = cid & 7;
            cp16(dst + row * 144 + g * 16, base + (size_t)row * (Dsz * 2) + g * 16);
        }
        commit_group();
    };

    auto produce_x = [&](int j) {
        uint32_t dst = sX + (j & 1) * STGA;
#pragma unroll
        for (int p = 0; p < 2; p++) {
            float4 v[8];
#pragma unroll
            for (int q = 0; q < 4; q++) {
                int cid = tid + (p * 4 + q) * 128;       // 0..1023
                int row = cid >> 3, gp = cid & 7;
                const float4* src = (const float4*)(xb + (size_t)row * (Dsz * 4) + j * 256 + gp * 32);
                v[q * 2]     = __ldg(src);
                v[q * 2 + 1] = __ldg(src + 1);
            }
#pragma unroll
            for (int q = 0; q < 4; q++) {
                int cid = tid + (p * 4 + q) * 128;
                int row = cid >> 3, gp = cid & 7;
                unsigned u0 = h2u(__floats2half2_rn(v[q*2].x,     v[q*2].y));
                unsigned u1 = h2u(__floats2half2_rn(v[q*2].z,     v[q*2].w));
                unsigned u2 = h2u(__floats2half2_rn(v[q*2+1].x,   v[q*2+1].y));
                unsigned u3 = h2u(__floats2half2_rn(v[q*2+1].z,   v[q*2+1].w));
                sts128(dst + row * 144 + gp * 16, u0, u1, u2, u3);
            }
        }
    };

    // prologue
    cp_A(0);
    cp_A(1);
    produce_x(0);
    asm volatile("cp.async.wait_group 1;" ::: "memory");
    __syncthreads();

    float acc[4][8][4] = {};

    const int KT = Dsz / 64;    // 20
#pragma unroll 1
    for (int kt = 0; kt < KT; kt++) {
        if (kt + 2 < KT) cp_A(kt + 2);
        else             commit_group();
        if (kt + 1 < KT) produce_x(kt + 1);

        uint32_t aS = sX + (kt & 1) * STGA;
        uint32_t bS = sA + (kt % 3) * STGA;

#pragma unroll
        for (int kk = 0; kk < 4; kk++) {
            unsigned af[4][4], bf[4][4];
            uint32_t kb = kk * 32;
#pragma unroll
            for (int i = 0; i < 4; i++) ldsm_x4(af[i], aS + aoff[i] + kb);
#pragma unroll
            for (int jp = 0; jp < 4; jp++) ldsm_x4(bf[jp], bS + boff[jp] + kb);
#pragma unroll
            for (int i = 0; i < 4; i++)
#pragma unroll
                for (int jp = 0; jp < 4; jp++) {
                    mma16816(acc[i][2*jp],   af[i], bf[jp][0], bf[jp][1]);
                    mma16816(acc[i][2*jp+1], af[i], bf[jp][2], bf[jp][3]);
                }
        }
        asm volatile("cp.async.wait_group 1;" ::: "memory");
        __syncthreads();
    }

    // epilogue: H (fp16) -> global
    __half* Hb = g_H + ((size_t)b * Ssz + m0) * 128;
#pragma unroll
    for (int i = 0; i < 4; i++) {
        int r = wm * 64 + i * 16 + lg;
#pragma unroll
        for (int j = 0; j < 8; j++) {
            int c = wn * 64 + j * 8 + lc * 2;
            *reinterpret_cast<__half2*>(Hb + (size_t)r * 128 + c) =
                __floats2half2_rn(acc[i][j][0], acc[i][j][1]);
            *reinterpret_cast<__half2*>(Hb + (size_t)(r + 8) * 128 + c) =
                __floats2half2_rn(acc[i][j][2], acc[i][j][3]);
        }
    }
}

// ---------------------------------------------------------------------------
// GEMM2: out[b] (4096x1280) = 2 * H[b] @ Bcat[b]^T.
// grid (32, 31), 128 thr. H tile in smem once; loop 10 n-tiles, B ring 2 stages.
// ---------------------------------------------------------------------------
__global__ __launch_bounds__(128) void gemm2_fp16(
    const int* __restrict__ label,
    float*     __restrict__ out)
{
    extern __shared__ char smem[];
    const int b   = blockIdx.y;
    const int m0  = blockIdx.x * 128;
    const int e   = __ldg(&label[b]);
    const int tid = threadIdx.x;
    const int warp = tid >> 5, lane = tid & 31;
    const int wm = warp & 1, wn = warp >> 1;
    const int lg = lane >> 2, lc = lane & 3;

    uint32_t sH = smem_u32(smem);
    uint32_t sB = sH + STGH;

    // ldmatrix per-lane offsets (stride 272)
    uint32_t aoff[4], boff[4];
#pragma unroll
    for (int i = 0; i < 4; i++)
        aoff[i] = (uint32_t)((wm * 64 + i * 16 + (lane & 15)) * 272 + ((lane >> 4) << 4));
#pragma unroll
    for (int jp = 0; jp < 4; jp++)
        boff[jp] = (uint32_t)((wn * 64 + jp * 16 + (lane & 7) + ((lane >> 4) << 3)) * 272
                              + (((lane >> 3) & 1) << 4));

    // H tile load (once)
    {
        const char* base = (const char*)g_H + ((size_t)b * Ssz + m0) * 256;
#pragma unroll
        for (int i = 0; i < 16; i++) {
            int cid = tid + i * 128;
            int row = cid >> 4, g = cid & 15;
            cp16(sH + row * 272 + g * 16, base + (size_t)row * 256 + g * 16);
        }
        commit_group();
    }

    auto cp_B = [&](int nt) {
        uint32_t dst = sB + (nt & 1) * STGH;
        const char* base = (const char*)g_Bcat + ((size_t)e * Dsz + nt * 128) * 256;
#pragma unroll
        for (int i = 0; i < 16; i++) {
            int cid = tid + i * 128;
            int row = cid >> 4, g = cid & 15;
            cp16(dst + row * 272 + g * 16, base + (size_t)row * 256 + g * 16);
        }
        commit_group();
    };

    cp_B(0);
    cp_B(1);
    asm volatile("cp.async.wait_group 1;" ::: "memory");   // H + B0 ready
    __syncthreads();

    float* ob = out + ((size_t)b * Ssz + m0) * Dsz;

#pragma unroll 1
    for (int nt = 0; nt < 10; nt++) {
        float acc[4][8][4] = {};
        uint32_t bS = sB + (nt & 1) * STGH;

#pragma unroll
        for (int kk = 0; kk < 8; kk++) {
            unsigned af[4][4], bf[4][4];
            uint32_t kb = kk * 32;
#pragma unroll
            for (int i = 0; i < 4; i++) ldsm_x4(af[i], sH + aoff[i] + kb);
#pragma unroll
            for (int jp = 0; jp < 4; jp++) ldsm_x4(bf[jp], bS + boff[jp] + kb);
#pragma unroll
            for (int i = 0; i < 4; i++)
#pragma unroll
                for (int jp = 0; jp < 4; jp++) {
                    mma16816(acc[i][2*jp],   af[i], bf[jp][0], bf[jp][1]);
                    mma16816(acc[i][2*jp+1], af[i], bf[jp][2], bf[jp][3]);
                }
        }

        asm volatile("cp.async.wait_group 0;" ::: "memory");
        __syncthreads();
        if (nt + 2 < 10) cp_B(nt + 2);

        // epilogue for this n-tile: out = 2*acc
        int n0 = nt * 128;
#pragma unroll
        for (int i = 0; i < 4; i++) {
            int r = wm * 64 + i * 16 + lg;
#pragma unroll
            for (int j = 0; j < 8; j++) {
                int c = n0 + wn * 64 + j * 8 + lc * 2;
                __stcs((float2*)&ob[(size_t)r * Dsz + c],
                       make_float2(2.0f * acc[i][j][0], 2.0f * acc[i][j][1]));
                __stcs((float2*)&ob[(size_t)(r + 8) * Dsz + c],
                       make_float2(2.0f * acc[i][j][2], 2.0f * acc[i][j][3]));
            }
        }
    }
}

// Zero out sample b = 31 (reference loops range(B-1))
__global__ void zero_last_kernel(float* __restrict__ out)
{
    size_t i = (size_t)blockIdx.x * blockDim.x + threadIdx.x;
    float4* p = (float4*)(out + (size_t)(Bsz - 1) * Ssz * Dsz);
    if (i < (size_t)Ssz * Dsz / 4)
        p[i] = make_float4(0.f, 0.f, 0.f, 0.f);
}

// ---------------------------------------------------------------------------
extern "C" void kernel_launch(void* const* d_in, const int* in_sizes, int n_in,
                              void* d_out, int out_size)
{
    const float* x     = (const float*)d_in[0];
    // d_in[1] = weight : unused by the reference
    const float* A_exp = (const float*)d_in[2];
    const float* B_exp = (const float*)d_in[3];
    const float* A_gen = (const float*)d_in[4];
    const float* B_gen = (const float*)d_in[5];
    const int*   label = (const int*)d_in[6];
    float* out = (float*)d_out;

    cudaFuncSetAttribute(gemm1_fp16, cudaFuncAttributeMaxDynamicSharedMemorySize, SMEM1);
    cudaFuncSetAttribute(gemm2_fp16, cudaFuncAttributeMaxDynamicSharedMemorySize, SMEM2);

    preconv_kernel<<<(8 * 128 * Dsz / 2 + 255) / 256, 256>>>(A_exp, B_exp, A_gen, B_gen);
    gemm1_fp16<<<dim3(Ssz / 128, Bsz - 1), 128, SMEM1>>>(x, label);
    gemm2_fp16<<<dim3(Ssz / 128, Bsz - 1), 128, SMEM2>>>(label, out);
    zero_last_kernel<<<(Ssz * Dsz / 4 + 255) / 256, 256>>>(out);
}

// round 5
// speedup vs baseline: 1.7293x; 1.2867x over previous
#include <cuda_runtime.h>
#include <cuda_fp16.h>
#include <cstdint>
#include <cstring>

#define Bsz 32
#define Ssz 4096
#define Dsz 1280
#define Rsz 64

// fp16 scratch: concatenated pre-rounded params + intermediate H
__device__ __half g_Acat[8 * 128 * Dsz];          // [e][n(128)][k(1280)]
__device__ __half g_Bcat[8 * Dsz * 128];          // [e][d(1280)][k(128)]
__device__ __half g_H[31u * Ssz * 128];           // [b][m][k(128)]

#define STGA 18432          // 128 rows x 144B (64 halves + pad)
#define STGH 34816          // 128 rows x 272B (128 halves + pad)
#define SMEM1 (2 * STGA + 3 * STGA)    // 92160
#define SMEM2 (STGH + 2 * STGH)        // 104448

// ---------------------------------------------------------------------------
__device__ __forceinline__ uint32_t smem_u32(const void* p) {
    uint32_t a;
    asm("{ .reg .u64 t; cvta.to.shared.u64 t, %1; cvt.u32.u64 %0, t; }" : "=r"(a) : "l"(p));
    return a;
}
__device__ __forceinline__ unsigned h2u(__half2 h) {
    unsigned u; memcpy(&u, &h, 4); return u;
}
__device__ __forceinline__ void cp16(uint32_t dst, const void* src) {
    asm volatile("cp.async.cg.shared.global [%0], [%1], 16;" :: "r"(dst), "l"(src));
}
__device__ __forceinline__ void commit_group() {
    asm volatile("cp.async.commit_group;" ::: "memory");
}
__device__ __forceinline__ void sts128(uint32_t a, unsigned u0, unsigned u1, unsigned u2, unsigned u3) {
    asm volatile("st.shared.v4.b32 [%0], {%1,%2,%3,%4};" :: "r"(a), "r"(u0), "r"(u1), "r"(u2), "r"(u3));
}
__device__ __forceinline__ void ldsm_x4(unsigned r[4], uint32_t addr) {
    asm volatile("ldmatrix.sync.aligned.m8n8.x4.shared.b16 {%0,%1,%2,%3}, [%4];"
                 : "=r"(r[0]), "=r"(r[1]), "=r"(r[2]), "=r"(r[3]) : "r"(addr));
}
__device__ __forceinline__ void mma16816(float c[4], const unsigned a[4], unsigned b0, unsigned b1) {
    asm volatile(
        "mma.sync.aligned.m16n8k16.row.col.f32.f16.f16.f32 "
        "{%0,%1,%2,%3}, {%4,%5,%6,%7}, {%8,%9}, {%0,%1,%2,%3};"
        : "+f"(c[0]), "+f"(c[1]), "+f"(c[2]), "+f"(c[3])
        : "r"(a[0]), "r"(a[1]), "r"(a[2]), "r"(a[3]), "r"(b0), "r"(b1));
}

// ---------------------------------------------------------------------------
// Pre-convert params to fp16 concatenated layouts (rn rounding).
// ---------------------------------------------------------------------------
__global__ void preconv_kernel(const float* __restrict__ A_exp,
                               const float* __restrict__ B_exp,
                               const float* __restrict__ A_gen,
                               const float* __restrict__ B_gen)
{
    int idx = blockIdx.x * blockDim.x + threadIdx.x;     // half2-pair index
    const int NA = 8 * 128 * Dsz / 2;                    // 655360
    if (idx < NA) {
        int p = idx * 2;
        int e = p / (128 * Dsz);
        int r = p % (128 * Dsz);
        int n = r / Dsz, k = r % Dsz;
        float f0, f1;
        if (n < Rsz) {
            const float* s = A_exp + ((size_t)e * Rsz + n) * Dsz + k;
            f0 = s[0]; f1 = s[1];
        } else {
            const float* s = A_gen + (size_t)(n - Rsz) * Dsz + k;
            f0 = s[0]; f1 = s[1];
        }
        *reinterpret_cast<__half2*>(&g_Acat[p]) = __floats2half2_rn(f0, f1);

        int e2 = p / (Dsz * 128);
        int r2 = p % (Dsz * 128);
        int d = r2 / 128, k2 = r2 % 128;
        float g0, g1;
        if (k2 < Rsz) {
            const float* s = B_exp + ((size_t)e2 * Dsz + d) * Rsz + k2;
            g0 = s[0]; g1 = s[1];
        } else {
            const float* s = B_gen + (size_t)d * Rsz + (k2 - Rsz);
            g0 = s[0]; g1 = s[1];
        }
        *reinterpret_cast<__half2*>(&g_Bcat[p]) = __floats2half2_rn(g0, g1);
    }
}

// ---------------------------------------------------------------------------
// GEMM1: H[b] (4096x128) = x[b] @ Acat[b]^T, fp16 mma, output fp16 to g_H.
// grid (32, 31), 256 thr (8 warps 4Mx2N, warp tile 32x64). K-stage 64, KT=20.
// ---------------------------------------------------------------------------
__global__ __launch_bounds__(256) void gemm1_fp16(
    const float* __restrict__ x,
    const int*   __restrict__ label)
{
    extern __shared__ char smem[];
    const int b   = blockIdx.y;
    const int m0  = blockIdx.x * 128;
    const int e   = __ldg(&label[b]);
    const int tid = threadIdx.x;
    const int warp = tid >> 5, lane = tid & 31;
    const int wm = warp & 3, wn = warp >> 2;
    const int lg = lane >> 2, lc = lane & 3;

    uint32_t sX = smem_u32(smem);                 // x ring: 2 stages
    uint32_t sA = sX + 2 * STGA;                  // Acat ring: 3 stages

    const char* xb = (const char*)(x + ((size_t)b * Ssz + m0) * Dsz);
    const char* Ab = (const char*)g_Acat + (size_t)e * 128 * Dsz * 2;

    // ldmatrix per-lane offsets (stride 144)
    uint32_t aoff[2], boff[4];
#pragma unroll
    for (int i = 0; i < 2; i++)
        aoff[i] = (uint32_t)((wm * 32 + i * 16 + (lane & 15)) * 144 + ((lane >> 4) << 4));
#pragma unroll
    for (int jp = 0; jp < 4; jp++)
        boff[jp] = (uint32_t)((wn * 64 + jp * 16 + (lane & 7) + ((lane >> 4) << 3)) * 144
                              + (((lane >> 3) & 1) << 4));

    auto cp_A = [&](int j) {
        uint32_t dst = sA + (j % 3) * STGA;
        const char* base = Ab + (size_t)j * 128;   // k-slice: 64 halves = 128B
#pragma unroll
        for (int i = 0; i < 4; i++) {
            int cid = tid + i * 256;               // 1024 chunks
            int row = cid >> 3, g = cid & 7;
            cp16(dst + row * 144 + g * 16, base + (size_t)row * (Dsz * 2) + g * 16);
        }
        commit_group();
    };

    auto produce_x = [&](int j) {
        uint32_t dst = sX + (j & 1) * STGA;
        float4 v[8];
#pragma unroll
        for (int q = 0; q < 4; q++) {
            int cid = tid + q * 256;               // 1024 chunks
            int row = cid >> 3, gp = cid & 7;
            const float4* src = (const float4*)(xb + (size_t)row * (Dsz * 4) + j * 256 + gp * 32);
            v[q * 2]     = __ldg(src);
            v[q * 2 + 1] = __ldg(src + 1);
        }
#pragma unroll
        for (int q = 0; q < 4; q++) {
            int cid = tid + q * 256;
            int row = cid >> 3, gp = cid & 7;
            unsigned u0 = h2u(__floats2half2_rn(v[q*2].x,   v[q*2].y));
            unsigned u1 = h2u(__floats2half2_rn(v[q*2].z,   v[q*2].w));
            unsigned u2 = h2u(__floats2half2_rn(v[q*2+1].x, v[q*2+1].y));
            unsigned u3 = h2u(__floats2half2_rn(v[q*2+1].z, v[q*2+1].w));
            sts128(dst + row * 144 + gp * 16, u0, u1, u2, u3);
        }
    };

    // prologue
    cp_A(0);
    cp_A(1);
    produce_x(0);
    asm volatile("cp.async.wait_group 1;" ::: "memory");
    __syncthreads();

    float acc[2][8][4] = {};

    const int KT = Dsz / 64;    // 20
#pragma unroll 1
    for (int kt = 0; kt < KT; kt++) {
        if (kt + 2 < KT) cp_A(kt + 2);
        else             commit_group();
        if (kt + 1 < KT) produce_x(kt + 1);

        uint32_t aS = sX + (kt & 1) * STGA;
        uint32_t bS = sA + (kt % 3) * STGA;

#pragma unroll
        for (int kk = 0; kk < 4; kk++) {
            unsigned af[2][4], bf[4][4];
            uint32_t kb = kk * 32;
#pragma unroll
            for (int i = 0; i < 2; i++) ldsm_x4(af[i], aS + aoff[i] + kb);
#pragma unroll
            for (int jp = 0; jp < 4; jp++) ldsm_x4(bf[jp], bS + boff[jp] + kb);
#pragma unroll
            for (int i = 0; i < 2; i++)
#pragma unroll
                for (int jp = 0; jp < 4; jp++) {
                    mma16816(acc[i][2*jp],   af[i], bf[jp][0], bf[jp][1]);
                    mma16816(acc[i][2*jp+1], af[i], bf[jp][2], bf[jp][3]);
                }
        }
        asm volatile("cp.async.wait_group 1;" ::: "memory");
        __syncthreads();
    }

    // epilogue: H (fp16) -> global
    __half* Hb = g_H + ((size_t)b * Ssz + m0) * 128;
#pragma unroll
    for (int i = 0; i < 2; i++) {
        int r = wm * 32 + i * 16 + lg;
#pragma unroll
        for (int j = 0; j < 8; j++) {
            int c = wn * 64 + j * 8 + lc * 2;
            *reinterpret_cast<__half2*>(Hb + (size_t)r * 128 + c) =
                __floats2half2_rn(acc[i][j][0], acc[i][j][1]);
            *reinterpret_cast<__half2*>(Hb + (size_t)(r + 8) * 128 + c) =
                __floats2half2_rn(acc[i][j][2], acc[i][j][3]);
        }
    }
}

// ---------------------------------------------------------------------------
// GEMM2: out[b] (4096x1280) = 2 * H[b] @ Bcat[b]^T.
// grid (32, 32), 256 thr. H tile in smem once; loop 10 n-tiles, B ring 2 stages.
// b==31 CTAs zero their 128x1280 slice.
// ---------------------------------------------------------------------------
__global__ __launch_bounds__(256) void gemm2_fp16(
    const int* __restrict__ label,
    float*     __restrict__ out)
{
    extern __shared__ char smem[];
    const int b   = blockIdx.y;
    const int m0  = blockIdx.x * 128;
    const int tid = threadIdx.x;

    float* ob = out + ((size_t)b * Ssz + m0) * Dsz;

    if (b == Bsz - 1) {
        float4 z = make_float4(0.f, 0.f, 0.f, 0.f);
#pragma unroll 4
        for (int i = 0; i < 160; i++) {
            int v = tid + i * 256;       // 40960 float4 = 128 rows x 320
            int row = v / 320, c4 = v % 320;
            __stcs((float4*)(ob + (size_t)row * Dsz + c4 * 4), z);
        }
        return;
    }

    const int e = __ldg(&label[b]);
    const int warp = tid >> 5, lane = tid & 31;
    const int wm = warp & 3, wn = warp >> 2;
    const int lg = lane >> 2, lc = lane & 3;

    uint32_t sH = smem_u32(smem);
    uint32_t sB = sH + STGH;

    // ldmatrix per-lane offsets (stride 272)
    uint32_t aoff[2], boff[4];
#pragma unroll
    for (int i = 0; i < 2; i++)
        aoff[i] = (uint32_t)((wm * 32 + i * 16 + (lane & 15)) * 272 + ((lane >> 4) << 4));
#pragma unroll
    for (int jp = 0; jp < 4; jp++)
        boff[jp] = (uint32_t)((wn * 64 + jp * 16 + (lane & 7) + ((lane >> 4) << 3)) * 272
                              + (((lane >> 3) & 1) << 4));

    // H tile load (once)
    {
        const char* base = (const char*)g_H + ((size_t)b * Ssz + m0) * 256;
#pragma unroll
        for (int i = 0; i < 8; i++) {
            int cid = tid + i * 256;               // 2048 chunks
            int row = cid >> 4, g = cid & 15;
            cp16(sH + row * 272 + g * 16, base + (size_t)row * 256 + g * 16);
        }
        commit_group();
    }

    auto cp_B = [&](int nt) {
        uint32_t dst = sB + (nt & 1) * STGH;
        const char* base = (const char*)g_Bcat + ((size_t)e * Dsz + nt * 128) * 256;
#pragma unroll
        for (int i = 0; i < 8; i++) {
            int cid = tid + i * 256;
            int row = cid >> 4, g = cid & 15;
            cp16(dst + row * 272 + g * 16, base + (size_t)row * 256 + g * 16);
        }
        commit_group();
    };

    cp_B(0);
    cp_B(1);
    asm volatile("cp.async.wait_group 1;" ::: "memory");   // H + B0 ready
    __syncthreads();

#pragma unroll 1
    for (int nt = 0; nt < 10; nt++) {
        float acc[2][8][4] = {};
        uint32_t bS = sB + (nt & 1) * STGH;

#pragma unroll
        for (int kk = 0; kk < 8; kk++) {
            unsigned af[2][4], bf[4][4];
            uint32_t kb = kk * 32;
#pragma unroll
            for (int i = 0; i < 2; i++) ldsm_x4(af[i], sH + aoff[i] + kb);
#pragma unroll
            for (int jp = 0; jp < 4; jp++) ldsm_x4(bf[jp], sB + (nt & 1) * STGH + boff[jp] + kb);
#pragma unroll
            for (int i = 0; i < 2; i++)
#pragma unroll
                for (int jp = 0; jp < 4; jp++) {
                    mma16816(acc[i][2*jp],   af[i], bf[jp][0], bf[jp][1]);
                    mma16816(acc[i][2*jp+1], af[i], bf[jp][2], bf[jp][3]);
                }
        }
        (void)bS;

        asm volatile("cp.async.wait_group 0;" ::: "memory");
        __syncthreads();
        if (nt + 2 < 10) cp_B(nt + 2);

        // epilogue for this n-tile: out = 2*acc
        int n0 = nt * 128;
#pragma unroll
        for (int i = 0; i < 2; i++) {
            int r = wm * 32 + i * 16 + lg;
#pragma unroll
            for (int j = 0; j < 8; j++) {
                int c = n0 + wn * 64 + j * 8 + lc * 2;
                __stcs((float2*)&ob[(size_t)r * Dsz + c],
                       make_float2(2.0f * acc[i][j][0], 2.0f * acc[i][j][1]));
                __stcs((float2*)&ob[(size_t)(r + 8) * Dsz + c],
                       make_float2(2.0f * acc[i][j][2], 2.0f * acc[i][j][3]));
            }
        }
    }
}

// ---------------------------------------------------------------------------
extern "C" void kernel_launch(void* const* d_in, const int* in_sizes, int n_in,
                              void* d_out, int out_size)
{
    const float* x     = (const float*)d_in[0];
    // d_in[1] = weight : unused by the reference
    const float* A_exp = (const float*)d_in[2];
    const float* B_exp = (const float*)d_in[3];
    const float* A_gen = (const float*)d_in[4];
    const float* B_gen = (const float*)d_in[5];
    const int*   label = (const int*)d_in[6];
    float* out = (float*)d_out;

    cudaFuncSetAttribute(gemm1_fp16, cudaFuncAttributeMaxDynamicSharedMemorySize, SMEM1);
    cudaFuncSetAttribute(gemm2_fp16, cudaFuncAttributeMaxDynamicSharedMemorySize, SMEM2);

    preconv_kernel<<<(8 * 128 * Dsz / 2 + 255) / 256, 256>>>(A_exp, B_exp, A_gen, B_gen);
    gemm1_fp16<<<dim3(Ssz / 128, Bsz - 1), 256, SMEM1>>>(x, label);
    gemm2_fp16<<<dim3(Ssz / 128, Bsz), 256, SMEM2>>>(label, out);
}